// round 12
// baseline (speedup 1.0000x reference)
#include <cuda_runtime.h>
#include <cuda_bf16.h>
#include <mma.h>
#include <cstdint>

using namespace nvcuda;

// ---------------- problem constants ----------------
#define N_NODES 50000
#define N_EDGES 800000
#define ET (N_EDGES + N_NODES)      // 850000 edges incl. self loops
#define D_IN 128
#define HC1 128                     // layer1 heads*ch = 4*32
#define D_OUT 64                    // layer2, 1 head of 64
#define SCAN_T 1024
#define NB ((N_NODES + SCAN_T - 1) / SCAN_T)   // 49
#define GK 128                      // K is 128 for every GEMM in this net
#define TM 128                      // M tile for tensor GEMM
#define MTILES ((N_NODES + TM - 1) / TM)       // 391
#define NPAD (MTILES * TM)          // 50048 rows: wmma stores need no M-guard

// ---------------- scratch (no allocs allowed) ----------------
__device__ float g_xl[NPAD * HC1];
__device__ float g_xr[NPAD * HC1];
__device__ float g_h [NPAD * HC1];
__device__ int   g_counts[N_NODES];
__device__ int   g_cursor[N_NODES];
__device__ int   g_rowptr[N_NODES + 1];
__device__ int   g_col[ET];
__device__ int   g_bsums[NB];

__device__ __forceinline__ float leaky(float v) {
    return (v > 0.f) ? v : 0.2f * v;
}

// ---------------- CSR construction ----------------
__global__ void count_k(const int* __restrict__ dstv, int* __restrict__ counts) {
    int e = blockIdx.x * blockDim.x + threadIdx.x;
    if (e >= ET) return;
    int d = (e < N_EDGES) ? dstv[e] : (e - N_EDGES);
    atomicAdd(&counts[d], 1);
}

__global__ void scan_block_k(const int* __restrict__ in, int* __restrict__ out,
                             int* __restrict__ bsums, int n) {
    __shared__ int sm[SCAN_T];
    int t = threadIdx.x;
    int i = blockIdx.x * SCAN_T + t;
    int v = (i < n) ? in[i] : 0;
    sm[t] = v;
    __syncthreads();
    #pragma unroll
    for (int off = 1; off < SCAN_T; off <<= 1) {
        int x = (t >= off) ? sm[t - off] : 0;
        __syncthreads();
        sm[t] += x;
        __syncthreads();
    }
    if (i < n) out[i] = sm[t] - v;              // exclusive
    if (t == SCAN_T - 1) bsums[blockIdx.x] = sm[t];
}

__global__ void scan_sums_k(int* bsums) {       // NB <= 64
    __shared__ int sm[64];
    int t = threadIdx.x;
    int v = (t < NB) ? bsums[t] : 0;
    sm[t] = v;
    __syncthreads();
    #pragma unroll
    for (int off = 1; off < 64; off <<= 1) {
        int x = (t >= off) ? sm[t - off] : 0;
        __syncthreads();
        sm[t] += x;
        __syncthreads();
    }
    if (t < NB) bsums[t] = sm[t] - v;           // exclusive
}

__global__ void scan_add_k(int* __restrict__ out, const int* __restrict__ bsums,
                           int n, int total) {
    int i = blockIdx.x * SCAN_T + threadIdx.x;
    if (i < n) out[i] += bsums[blockIdx.x];
    if (i == n) out[n] = total;
}

__global__ void scatter_k(const int* __restrict__ srcv, const int* __restrict__ dstv,
                          const int* __restrict__ rowptr, int* __restrict__ cursor,
                          int* __restrict__ colv) {
    int e = blockIdx.x * blockDim.x + threadIdx.x;
    if (e >= ET) return;
    int d, s;
    if (e < N_EDGES) { d = dstv[e]; s = srcv[e]; }
    else             { d = s = e - N_EDGES; }
    int pos = rowptr[d] + atomicAdd(&cursor[d], 1);
    colv[pos] = s;
}

// ---------------- dual-output tensor-core GEMM (bf16 split, wmma) ----------------
// C1 = A@B1, C2 = A@B2 (no bias; biases folded into attention kernels).
// A fp32 [M,128], Bx fp32 [128,N]. Split each fp32 into bf16 hi+lo
// (a = hi + lo exact to ~16 mantissa bits); per k-tile issue
// acc += Ahi*Bhi + Ahi*Blo + Alo*Bhi  ->  ~1e-5 rel error, tensor-pipe rate.
// wmma m16n16k16 bf16 compiles for plain sm_103 (tcgen05 is 'a'-gated and
// unavailable in this harness).  One CTA = 128 rows x both outputs x K=128.
__global__ void __launch_bounds__(256)
gemm_tc_k(const float* __restrict__ A,
          const float* __restrict__ B1, const float* __restrict__ B2,
          float* __restrict__ C1, float* __restrict__ C2,
          int M, int N) {
    extern __shared__ char smem[];
    __nv_bfloat16* Ah  = (__nv_bfloat16*)smem;          // [128][128]
    __nv_bfloat16* Al  = Ah  + TM * GK;
    __nv_bfloat16* Bh1 = Al  + TM * GK;                 // [128][N]
    __nv_bfloat16* Bl1 = Bh1 + GK * N;
    __nv_bfloat16* Bh2 = Bl1 + GK * N;
    __nv_bfloat16* Bl2 = Bh2 + GK * N;

    int tid  = threadIdx.x;
    int row0 = blockIdx.x * TM;

    // ---- stage A (guarded, zero-fill OOB rows), bf16 hi/lo split ----
    for (int i = tid * 4; i < TM * GK; i += 256 * 4) {
        int m = i >> 7, k = i & 127;
        float4 v = make_float4(0.f, 0.f, 0.f, 0.f);
        if (row0 + m < M) v = *(const float4*)(A + (size_t)(row0 + m) * GK + k);
        __nv_bfloat16 hx = __float2bfloat16(v.x), hy = __float2bfloat16(v.y);
        __nv_bfloat16 hz = __float2bfloat16(v.z), hw = __float2bfloat16(v.w);
        *(__nv_bfloat162*)(Ah + i)     = __halves2bfloat162(hx, hy);
        *(__nv_bfloat162*)(Ah + i + 2) = __halves2bfloat162(hz, hw);
        __nv_bfloat16 lx = __float2bfloat16(v.x - __bfloat162float(hx));
        __nv_bfloat16 ly = __float2bfloat16(v.y - __bfloat162float(hy));
        __nv_bfloat16 lz = __float2bfloat16(v.z - __bfloat162float(hz));
        __nv_bfloat16 lw = __float2bfloat16(v.w - __bfloat162float(hw));
        *(__nv_bfloat162*)(Al + i)     = __halves2bfloat162(lx, ly);
        *(__nv_bfloat162*)(Al + i + 2) = __halves2bfloat162(lz, lw);
    }
    // ---- stage B1, B2 ([K,N] row-major, direct) ----
    for (int i = tid * 4; i < GK * N; i += 256 * 4) {
        float4 v1 = *(const float4*)(B1 + i);
        float4 v2 = *(const float4*)(B2 + i);
        {
            __nv_bfloat16 hx = __float2bfloat16(v1.x), hy = __float2bfloat16(v1.y);
            __nv_bfloat16 hz = __float2bfloat16(v1.z), hw = __float2bfloat16(v1.w);
            *(__nv_bfloat162*)(Bh1 + i)     = __halves2bfloat162(hx, hy);
            *(__nv_bfloat162*)(Bh1 + i + 2) = __halves2bfloat162(hz, hw);
            __nv_bfloat16 lx = __float2bfloat16(v1.x - __bfloat162float(hx));
            __nv_bfloat16 ly = __float2bfloat16(v1.y - __bfloat162float(hy));
            __nv_bfloat16 lz = __float2bfloat16(v1.z - __bfloat162float(hz));
            __nv_bfloat16 lw = __float2bfloat16(v1.w - __bfloat162float(hw));
            *(__nv_bfloat162*)(Bl1 + i)     = __halves2bfloat162(lx, ly);
            *(__nv_bfloat162*)(Bl1 + i + 2) = __halves2bfloat162(lz, lw);
        }
        {
            __nv_bfloat16 hx = __float2bfloat16(v2.x), hy = __float2bfloat16(v2.y);
            __nv_bfloat16 hz = __float2bfloat16(v2.z), hw = __float2bfloat16(v2.w);
            *(__nv_bfloat162*)(Bh2 + i)     = __halves2bfloat162(hx, hy);
            *(__nv_bfloat162*)(Bh2 + i + 2) = __halves2bfloat162(hz, hw);
            __nv_bfloat16 lx = __float2bfloat16(v2.x - __bfloat162float(hx));
            __nv_bfloat16 ly = __float2bfloat16(v2.y - __bfloat162float(hy));
            __nv_bfloat16 lz = __float2bfloat16(v2.z - __bfloat162float(hz));
            __nv_bfloat16 lw = __float2bfloat16(v2.w - __bfloat162float(hw));
            *(__nv_bfloat162*)(Bl2 + i)     = __halves2bfloat162(lx, ly);
            *(__nv_bfloat162*)(Bl2 + i + 2) = __halves2bfloat162(lz, lw);
        }
    }
    __syncthreads();

    // ---- compute: warp w owns rows [w*16, w*16+16) of the tile ----
    int w = tid >> 5;
    int mrow = w * 16;
    int ctiles = N >> 4;                 // col tiles per output
    int total  = 2 * ctiles;             // both outputs

    for (int c0 = 0; c0 < total; c0 += 4) {
        wmma::fragment<wmma::accumulator, 16, 16, 16, float> acc[4];
        #pragma unroll
        for (int t = 0; t < 4; t++) wmma::fill_fragment(acc[t], 0.f);

        for (int ks = 0; ks < GK / 16; ks++) {
            wmma::fragment<wmma::matrix_a, 16, 16, 16, __nv_bfloat16,
                           wmma::row_major> ah, al;
            wmma::load_matrix_sync(ah, Ah + mrow * GK + ks * 16, GK);
            wmma::load_matrix_sync(al, Al + mrow * GK + ks * 16, GK);
            #pragma unroll
            for (int t = 0; t < 4; t++) {
                int ct   = c0 + t;
                int outi = (ct >= ctiles);
                int n0   = (ct - outi * ctiles) * 16;
                const __nv_bfloat16* bh = outi ? Bh2 : Bh1;
                const __nv_bfloat16* bl = outi ? Bl2 : Bl1;
                wmma::fragment<wmma::matrix_b, 16, 16, 16, __nv_bfloat16,
                               wmma::row_major> bhf, blf;
                wmma::load_matrix_sync(bhf, bh + ks * 16 * N + n0, N);
                wmma::load_matrix_sync(blf, bl + ks * 16 * N + n0, N);
                wmma::mma_sync(acc[t], ah, bhf, acc[t]);
                wmma::mma_sync(acc[t], ah, blf, acc[t]);
                wmma::mma_sync(acc[t], al, bhf, acc[t]);
            }
        }
        #pragma unroll
        for (int t = 0; t < 4; t++) {
            int ct   = c0 + t;
            int outi = (ct >= ctiles);
            int n0   = (ct - outi * ctiles) * 16;
            float* C = outi ? C2 : C1;
            wmma::store_matrix_sync(C + (size_t)(row0 + mrow) * N + n0,
                                    acc[t], N, wmma::mem_row_major);
        }
    }
}

// ---------------- fused GATv2 attention+aggregation ----------------
// Biases of the linear transforms (bl -> msg side, br -> target side) are
// folded here since the tensor GEMM skips them.
// Layer 1: warp per node, lane = float4 of channels, 8 lanes/head, 4 heads.
__global__ void __launch_bounds__(256)
attn_l1_k(const float* __restrict__ xl, const float* __restrict__ xr,
          const float* __restrict__ bl, const float* __restrict__ br,
          const float* __restrict__ att, const float* __restrict__ bias,
          const int* __restrict__ rowptr, const int* __restrict__ colv,
          float* __restrict__ out) {
    int node = (blockIdx.x * blockDim.x + threadIdx.x) >> 5;
    if (node >= N_NODES) return;
    int lane = threadIdx.x & 31;
    int c4 = lane * 4;
    float4 a4  = *(const float4*)(att + c4);
    float4 bl4 = *(const float4*)(bl + c4);
    float4 xr4 = *(const float4*)(xr + (size_t)node * HC1 + c4);
    {
        float4 br4 = *(const float4*)(br + c4);
        xr4.x += br4.x; xr4.y += br4.y; xr4.z += br4.z; xr4.w += br4.w;
    }
    int beg = rowptr[node], end = rowptr[node + 1];
    float4 acc = make_float4(0.f, 0.f, 0.f, 0.f);
    float denom = 0.f;
    int idx = beg;
    for (; idx + 2 <= end; idx += 2) {
        int j0 = colv[idx], j1 = colv[idx + 1];
        float4 m0 = __ldg((const float4*)(xl + (size_t)j0 * HC1 + c4));
        float4 m1 = __ldg((const float4*)(xl + (size_t)j1 * HC1 + c4));
        m0.x += bl4.x; m0.y += bl4.y; m0.z += bl4.z; m0.w += bl4.w;
        m1.x += bl4.x; m1.y += bl4.y; m1.z += bl4.z; m1.w += bl4.w;
        float s0 = leaky(m0.x + xr4.x) * a4.x;
        s0 = fmaf(leaky(m0.y + xr4.y), a4.y, s0);
        s0 = fmaf(leaky(m0.z + xr4.z), a4.z, s0);
        s0 = fmaf(leaky(m0.w + xr4.w), a4.w, s0);
        float s1 = leaky(m1.x + xr4.x) * a4.x;
        s1 = fmaf(leaky(m1.y + xr4.y), a4.y, s1);
        s1 = fmaf(leaky(m1.z + xr4.z), a4.z, s1);
        s1 = fmaf(leaky(m1.w + xr4.w), a4.w, s1);
        #pragma unroll
        for (int o = 4; o; o >>= 1) {
            s0 += __shfl_xor_sync(0xffffffffu, s0, o);
            s1 += __shfl_xor_sync(0xffffffffu, s1, o);
        }
        float x0 = __expf(s0), x1 = __expf(s1);
        denom += x0 + x1;
        acc.x = fmaf(x0, m0.x, acc.x); acc.y = fmaf(x0, m0.y, acc.y);
        acc.z = fmaf(x0, m0.z, acc.z); acc.w = fmaf(x0, m0.w, acc.w);
        acc.x = fmaf(x1, m1.x, acc.x); acc.y = fmaf(x1, m1.y, acc.y);
        acc.z = fmaf(x1, m1.z, acc.z); acc.w = fmaf(x1, m1.w, acc.w);
    }
    if (idx < end) {
        int j = colv[idx];
        float4 m = __ldg((const float4*)(xl + (size_t)j * HC1 + c4));
        m.x += bl4.x; m.y += bl4.y; m.z += bl4.z; m.w += bl4.w;
        float s = leaky(m.x + xr4.x) * a4.x;
        s = fmaf(leaky(m.y + xr4.y), a4.y, s);
        s = fmaf(leaky(m.z + xr4.z), a4.z, s);
        s = fmaf(leaky(m.w + xr4.w), a4.w, s);
        #pragma unroll
        for (int o = 4; o; o >>= 1) s += __shfl_xor_sync(0xffffffffu, s, o);
        float ex = __expf(s);
        denom += ex;
        acc.x = fmaf(ex, m.x, acc.x); acc.y = fmaf(ex, m.y, acc.y);
        acc.z = fmaf(ex, m.z, acc.z); acc.w = fmaf(ex, m.w, acc.w);
    }
    float inv = 1.f / denom;
    float4 b4 = *(const float4*)(bias + c4);
    float4 o4;
    o4.x = fmaxf(fmaf(acc.x, inv, b4.x), 0.f);
    o4.y = fmaxf(fmaf(acc.y, inv, b4.y), 0.f);
    o4.z = fmaxf(fmaf(acc.z, inv, b4.z), 0.f);
    o4.w = fmaxf(fmaf(acc.w, inv, b4.w), 0.f);
    *(float4*)(out + (size_t)node * HC1 + c4) = o4;     // fused ReLU
}

// Layer 2: warp per node; two half-warps process two edges at once.
__global__ void __launch_bounds__(256)
attn_l2_k(const float* __restrict__ xl, const float* __restrict__ xr,
          const float* __restrict__ bl, const float* __restrict__ br,
          const float* __restrict__ att, const float* __restrict__ bias,
          const int* __restrict__ rowptr, const int* __restrict__ colv,
          float* __restrict__ out) {
    int node = (blockIdx.x * blockDim.x + threadIdx.x) >> 5;
    if (node >= N_NODES) return;
    int lane = threadIdx.x & 31;
    int half = lane >> 4;
    int sl   = lane & 15;
    int c4   = sl * 4;
    float4 a4  = *(const float4*)(att + c4);
    float4 bl4 = *(const float4*)(bl + c4);
    float4 xr4 = *(const float4*)(xr + (size_t)node * D_OUT + c4);
    {
        float4 br4 = *(const float4*)(br + c4);
        xr4.x += br4.x; xr4.y += br4.y; xr4.z += br4.z; xr4.w += br4.w;
    }
    int beg = rowptr[node], end = rowptr[node + 1];
    float4 acc = make_float4(0.f, 0.f, 0.f, 0.f);
    float denom = 0.f;
    for (int idx = beg; idx < end; idx += 2) {
        int e = idx + half;
        bool valid = (e < end);
        int j = colv[valid ? e : (end - 1)];
        float4 m = __ldg((const float4*)(xl + (size_t)j * D_OUT + c4));
        m.x += bl4.x; m.y += bl4.y; m.z += bl4.z; m.w += bl4.w;
        float s = leaky(m.x + xr4.x) * a4.x;
        s = fmaf(leaky(m.y + xr4.y), a4.y, s);
        s = fmaf(leaky(m.z + xr4.z), a4.z, s);
        s = fmaf(leaky(m.w + xr4.w), a4.w, s);
        #pragma unroll
        for (int o = 8; o; o >>= 1) s += __shfl_xor_sync(0xffffffffu, s, o);
        float ex = valid ? __expf(s) : 0.f;
        denom += ex;
        acc.x = fmaf(ex, m.x, acc.x); acc.y = fmaf(ex, m.y, acc.y);
        acc.z = fmaf(ex, m.z, acc.z); acc.w = fmaf(ex, m.w, acc.w);
    }
    denom += __shfl_xor_sync(0xffffffffu, denom, 16);
    acc.x += __shfl_xor_sync(0xffffffffu, acc.x, 16);
    acc.y += __shfl_xor_sync(0xffffffffu, acc.y, 16);
    acc.z += __shfl_xor_sync(0xffffffffu, acc.z, 16);
    acc.w += __shfl_xor_sync(0xffffffffu, acc.w, 16);
    if (half == 0) {
        float inv = 1.f / denom;
        float4 b4 = *(const float4*)(bias + c4);
        float4 o4;
        o4.x = fmaf(acc.x, inv, b4.x);
        o4.y = fmaf(acc.y, inv, b4.y);
        o4.z = fmaf(acc.z, inv, b4.z);
        o4.w = fmaf(acc.w, inv, b4.w);
        *(float4*)(out + (size_t)node * D_OUT + c4) = o4;
    }
}

// ---------------- host launcher ----------------
extern "C" void kernel_launch(void* const* d_in, const int* in_sizes, int n_in,
                              void* d_out, int out_size) {
    const float* x     = (const float*)d_in[0];
    const int*   ei    = (const int*)  d_in[1];
    const float* Wl1   = (const float*)d_in[2];
    const float* bl1   = (const float*)d_in[3];
    const float* Wr1   = (const float*)d_in[4];
    const float* br1   = (const float*)d_in[5];
    const float* att1  = (const float*)d_in[6];
    const float* bias1 = (const float*)d_in[7];
    const float* Wl2   = (const float*)d_in[8];
    const float* bl2   = (const float*)d_in[9];
    const float* Wr2   = (const float*)d_in[10];
    const float* br2   = (const float*)d_in[11];
    const float* att2  = (const float*)d_in[12];
    const float* bias2 = (const float*)d_in[13];
    float* out = (float*)d_out;

    float *xl, *xr, *h;
    int *counts, *cursor, *rowptr, *colv, *bsums;
    cudaGetSymbolAddress((void**)&xl,     g_xl);
    cudaGetSymbolAddress((void**)&xr,     g_xr);
    cudaGetSymbolAddress((void**)&h,      g_h);
    cudaGetSymbolAddress((void**)&counts, g_counts);
    cudaGetSymbolAddress((void**)&cursor, g_cursor);
    cudaGetSymbolAddress((void**)&rowptr, g_rowptr);
    cudaGetSymbolAddress((void**)&colv,   g_col);
    cudaGetSymbolAddress((void**)&bsums,  g_bsums);

    const int* srcv = ei;
    const int* dstv = ei + N_EDGES;

    // smem: A hi+lo (2*128*128*2B = 64KB) + 4 B planes (hi/lo x 2 outputs)
    const int smem1 = (2 * TM * GK + 4 * GK * HC1)   * 2;   // 196608 B
    const int smem2 = (2 * TM * GK + 4 * GK * D_OUT) * 2;   // 131072 B
    cudaFuncSetAttribute(gemm_tc_k,
        cudaFuncAttributeMaxDynamicSharedMemorySize, smem1);

    int attn_blocks = (N_NODES * 32 + 255) / 256;   // warp per node

    // gemm layer1 at kernel-launch index 3 (ncu capture window).
    cudaMemsetAsync(counts, 0, N_NODES * sizeof(int));
    cudaMemsetAsync(cursor, 0, N_NODES * sizeof(int));
    count_k     <<<(ET + 255) / 256, 256>>>(dstv, counts);                     // 0
    scan_block_k<<<NB, SCAN_T>>>(counts, rowptr, bsums, N_NODES);              // 1
    scan_sums_k <<<1, 64>>>(bsums);                                            // 2
    gemm_tc_k   <<<MTILES, 256, smem1>>>(x, Wl1, Wr1, xl, xr, N_NODES, HC1);   // 3
    scan_add_k  <<<NB, SCAN_T>>>(rowptr, bsums, N_NODES, ET);                  // 4
    scatter_k   <<<(ET + 255) / 256, 256>>>(srcv, dstv, rowptr, cursor, colv); // 5
    attn_l1_k   <<<attn_blocks, 256>>>(xl, xr, bl1, br1, att1, bias1,
                                       rowptr, colv, h);                       // 6
    gemm_tc_k   <<<MTILES, 256, smem2>>>(h, Wl2, Wr2, xl, xr, N_NODES, D_OUT); // 7
    attn_l2_k   <<<attn_blocks, 256>>>(xl, xr, bl2, br2, att2, bias2,
                                       rowptr, colv, out);                     // 8
}

// round 17
// speedup vs baseline: 1.1420x; 1.1420x over previous
#include <cuda_runtime.h>
#include <cuda_bf16.h>
#include <mma.h>
#include <cstdint>

using namespace nvcuda;

// ---------------- problem constants ----------------
#define N_NODES 50000
#define N_EDGES 800000
#define ET (N_EDGES + N_NODES)      // 850000 edges incl. self loops
#define D_IN 128
#define HC1 128                     // layer1 heads*ch = 4*32
#define D_OUT 64                    // layer2, 1 head of 64
#define SCAN_T 1024
#define NB ((N_NODES + SCAN_T - 1) / SCAN_T)   // 49
#define GK 128                      // K is 128 for every GEMM in this net
#define TM 128                      // M tile for tensor GEMM
#define MTILES ((N_NODES + TM - 1) / TM)       // 391
#define NPAD (MTILES * TM)          // 50048 rows: wmma stores need no M-guard
#define LDA (GK + 8)                // padded A stride: 272B -> conflict-free ldmatrix

// ---------------- scratch (no allocs allowed) ----------------
__device__ float g_xl[NPAD * HC1];
__device__ float g_xr[NPAD * HC1];
__device__ float g_h [NPAD * HC1];
__device__ int   g_counts[N_NODES];
__device__ int   g_cursor[N_NODES];
__device__ int   g_rowptr[N_NODES + 1];
__device__ int   g_col[ET];
__device__ int   g_bsums[NB];

__device__ __forceinline__ float leaky(float v) {
    return (v > 0.f) ? v : 0.2f * v;
}

// ---------------- CSR construction ----------------
__global__ void count_k(const int* __restrict__ dstv, int* __restrict__ counts) {
    int e = blockIdx.x * blockDim.x + threadIdx.x;
    if (e >= ET) return;
    int d = (e < N_EDGES) ? dstv[e] : (e - N_EDGES);
    atomicAdd(&counts[d], 1);
}

__global__ void scan_block_k(const int* __restrict__ in, int* __restrict__ out,
                             int* __restrict__ bsums, int n) {
    __shared__ int sm[SCAN_T];
    int t = threadIdx.x;
    int i = blockIdx.x * SCAN_T + t;
    int v = (i < n) ? in[i] : 0;
    sm[t] = v;
    __syncthreads();
    #pragma unroll
    for (int off = 1; off < SCAN_T; off <<= 1) {
        int x = (t >= off) ? sm[t - off] : 0;
        __syncthreads();
        sm[t] += x;
        __syncthreads();
    }
    if (i < n) out[i] = sm[t] - v;              // exclusive
    if (t == SCAN_T - 1) bsums[blockIdx.x] = sm[t];
}

__global__ void scan_sums_k(int* bsums) {       // NB <= 64
    __shared__ int sm[64];
    int t = threadIdx.x;
    int v = (t < NB) ? bsums[t] : 0;
    sm[t] = v;
    __syncthreads();
    #pragma unroll
    for (int off = 1; off < 64; off <<= 1) {
        int x = (t >= off) ? sm[t - off] : 0;
        __syncthreads();
        sm[t] += x;
        __syncthreads();
    }
    if (t < NB) bsums[t] = sm[t] - v;           // exclusive
}

__global__ void scan_add_k(int* __restrict__ out, const int* __restrict__ bsums,
                           int n, int total) {
    int i = blockIdx.x * SCAN_T + threadIdx.x;
    if (i < n) out[i] += bsums[blockIdx.x];
    if (i == n) out[n] = total;
}

__global__ void scatter_k(const int* __restrict__ srcv, const int* __restrict__ dstv,
                          const int* __restrict__ rowptr, int* __restrict__ cursor,
                          int* __restrict__ colv) {
    int e = blockIdx.x * blockDim.x + threadIdx.x;
    if (e >= ET) return;
    int d, s;
    if (e < N_EDGES) { d = dstv[e]; s = srcv[e]; }
    else             { d = s = e - N_EDGES; }
    int pos = rowptr[d] + atomicAdd(&cursor[d], 1);
    colv[pos] = s;
}

// ---------------- dual-output tensor-core GEMM (bf16 split, wmma) ----------------
// C1 = A@B1, C2 = A@B2 (biases folded into attention kernels).
// bf16 two-term split: acc += Ahi*Bhi + Ahi*Blo + Alo*Bhi -> ~4e-6 rel err.
// R12 profile: tensor 8.7%, L1 69% -> smem-conflict bound. Fixes:
//  - +8-element padding on every plane (row stride 272B / 144B): ldmatrix rows
//    shift 4 banks per row -> conflict-free.
//  - 4(M)x2(N) warp grid, acc[2][4]: each B fragment feeds 6 MMAs, per-warp
//    fragment loads drop 320 -> 192.
__global__ void __launch_bounds__(256)
gemm_tc_k(const float* __restrict__ A,
          const float* __restrict__ B1, const float* __restrict__ B2,
          float* __restrict__ C1, float* __restrict__ C2,
          int M, int N) {
    extern __shared__ char smem[];
    const int LDB = N + 8;
    __nv_bfloat16* Ah  = (__nv_bfloat16*)smem;          // [128][LDA]
    __nv_bfloat16* Al  = Ah  + TM * LDA;
    __nv_bfloat16* Bh1 = Al  + TM * LDA;                // [128][LDB]
    __nv_bfloat16* Bl1 = Bh1 + GK * LDB;
    __nv_bfloat16* Bh2 = Bl1 + GK * LDB;
    __nv_bfloat16* Bl2 = Bh2 + GK * LDB;

    int tid  = threadIdx.x;
    int row0 = blockIdx.x * TM;

    // ---- stage A (guarded, zero-fill OOB rows), bf16 hi/lo split ----
    for (int i = tid * 4; i < TM * GK; i += 256 * 4) {
        int m = i >> 7, k = i & 127;
        float4 v = make_float4(0.f, 0.f, 0.f, 0.f);
        if (row0 + m < M) v = *(const float4*)(A + (size_t)(row0 + m) * GK + k);
        int d = m * LDA + k;
        __nv_bfloat16 hx = __float2bfloat16(v.x), hy = __float2bfloat16(v.y);
        __nv_bfloat16 hz = __float2bfloat16(v.z), hw = __float2bfloat16(v.w);
        *(__nv_bfloat162*)(Ah + d)     = __halves2bfloat162(hx, hy);
        *(__nv_bfloat162*)(Ah + d + 2) = __halves2bfloat162(hz, hw);
        *(__nv_bfloat162*)(Al + d) = __halves2bfloat162(
            __float2bfloat16(v.x - __bfloat162float(hx)),
            __float2bfloat16(v.y - __bfloat162float(hy)));
        *(__nv_bfloat162*)(Al + d + 2) = __halves2bfloat162(
            __float2bfloat16(v.z - __bfloat162float(hz)),
            __float2bfloat16(v.w - __bfloat162float(hw)));
    }
    // ---- stage B1, B2 ([K,N] row-major, padded) ----
    for (int i = tid * 4; i < GK * N; i += 256 * 4) {
        int k = i / N, n = i - k * N;
        int d = k * LDB + n;
        float4 v1 = *(const float4*)(B1 + i);
        float4 v2 = *(const float4*)(B2 + i);
        {
            __nv_bfloat16 hx = __float2bfloat16(v1.x), hy = __float2bfloat16(v1.y);
            __nv_bfloat16 hz = __float2bfloat16(v1.z), hw = __float2bfloat16(v1.w);
            *(__nv_bfloat162*)(Bh1 + d)     = __halves2bfloat162(hx, hy);
            *(__nv_bfloat162*)(Bh1 + d + 2) = __halves2bfloat162(hz, hw);
            *(__nv_bfloat162*)(Bl1 + d) = __halves2bfloat162(
                __float2bfloat16(v1.x - __bfloat162float(hx)),
                __float2bfloat16(v1.y - __bfloat162float(hy)));
            *(__nv_bfloat162*)(Bl1 + d + 2) = __halves2bfloat162(
                __float2bfloat16(v1.z - __bfloat162float(hz)),
                __float2bfloat16(v1.w - __bfloat162float(hw)));
        }
        {
            __nv_bfloat16 hx = __float2bfloat16(v2.x), hy = __float2bfloat16(v2.y);
            __nv_bfloat16 hz = __float2bfloat16(v2.z), hw = __float2bfloat16(v2.w);
            *(__nv_bfloat162*)(Bh2 + d)     = __halves2bfloat162(hx, hy);
            *(__nv_bfloat162*)(Bh2 + d + 2) = __halves2bfloat162(hz, hw);
            *(__nv_bfloat162*)(Bl2 + d) = __halves2bfloat162(
                __float2bfloat16(v2.x - __bfloat162float(hx)),
                __float2bfloat16(v2.y - __bfloat162float(hy)));
            *(__nv_bfloat162*)(Bl2 + d + 2) = __halves2bfloat162(
                __float2bfloat16(v2.z - __bfloat162float(hz)),
                __float2bfloat16(v2.w - __bfloat162float(hw)));
        }
    }
    __syncthreads();

    // ---- compute: warp grid 4(M) x 2(N) ----
    int wid = tid >> 5;
    int wm  = wid >> 1;                  // 0..3 -> rows [wm*32, +32)
    int wn  = wid & 1;                   // 0..1 -> half of all column tiles
    int ctiles = N >> 4;                 // col tiles per output
    int total  = 2 * ctiles;             // both outputs
    int half   = total >> 1;

    for (int c0 = wn * half; c0 < wn * half + half; c0 += 4) {
        wmma::fragment<wmma::accumulator, 16, 16, 16, float> acc[2][4];
        #pragma unroll
        for (int mi = 0; mi < 2; mi++)
            #pragma unroll
            for (int t = 0; t < 4; t++) wmma::fill_fragment(acc[mi][t], 0.f);

        for (int ks = 0; ks < GK / 16; ks++) {
            wmma::fragment<wmma::matrix_a, 16, 16, 16, __nv_bfloat16,
                           wmma::row_major> ah[2], al[2];
            #pragma unroll
            for (int mi = 0; mi < 2; mi++) {
                int mrow = wm * 32 + mi * 16;
                wmma::load_matrix_sync(ah[mi], Ah + mrow * LDA + ks * 16, LDA);
                wmma::load_matrix_sync(al[mi], Al + mrow * LDA + ks * 16, LDA);
            }
            #pragma unroll
            for (int t = 0; t < 4; t++) {
                int ct   = c0 + t;
                int outi = (ct >= ctiles);
                int n0   = (ct - outi * ctiles) * 16;
                const __nv_bfloat16* bh = outi ? Bh2 : Bh1;
                const __nv_bfloat16* bl = outi ? Bl2 : Bl1;
                wmma::fragment<wmma::matrix_b, 16, 16, 16, __nv_bfloat16,
                               wmma::row_major> bhf, blf;
                wmma::load_matrix_sync(bhf, bh + ks * 16 * LDB + n0, LDB);
                wmma::load_matrix_sync(blf, bl + ks * 16 * LDB + n0, LDB);
                #pragma unroll
                for (int mi = 0; mi < 2; mi++) {
                    wmma::mma_sync(acc[mi][t], ah[mi], bhf, acc[mi][t]);
                    wmma::mma_sync(acc[mi][t], ah[mi], blf, acc[mi][t]);
                    wmma::mma_sync(acc[mi][t], al[mi], bhf, acc[mi][t]);
                }
            }
        }
        #pragma unroll
        for (int t = 0; t < 4; t++) {
            int ct   = c0 + t;
            int outi = (ct >= ctiles);
            int n0   = (ct - outi * ctiles) * 16;
            float* C = outi ? C2 : C1;
            #pragma unroll
            for (int mi = 0; mi < 2; mi++) {
                int mrow = wm * 32 + mi * 16;
                wmma::store_matrix_sync(C + (size_t)(row0 + mrow) * N + n0,
                                        acc[mi][t], N, wmma::mem_row_major);
            }
        }
    }
}

// ---------------- fused GATv2 attention+aggregation ----------------
// Linear-transform biases (bl -> msg side, br -> target side) folded here.
// Layer 1: warp per node, lane = float4 of channels, 8 lanes/head, 4 heads.
__global__ void __launch_bounds__(256)
attn_l1_k(const float* __restrict__ xl, const float* __restrict__ xr,
          const float* __restrict__ bl, const float* __restrict__ br,
          const float* __restrict__ att, const float* __restrict__ bias,
          const int* __restrict__ rowptr, const int* __restrict__ colv,
          float* __restrict__ out) {
    int node = (blockIdx.x * blockDim.x + threadIdx.x) >> 5;
    if (node >= N_NODES) return;
    int lane = threadIdx.x & 31;
    int c4 = lane * 4;
    float4 a4  = *(const float4*)(att + c4);
    float4 bl4 = *(const float4*)(bl + c4);
    float4 xr4 = *(const float4*)(xr + (size_t)node * HC1 + c4);
    {
        float4 br4 = *(const float4*)(br + c4);
        xr4.x += br4.x; xr4.y += br4.y; xr4.z += br4.z; xr4.w += br4.w;
    }
    int beg = rowptr[node], end = rowptr[node + 1];
    float4 acc = make_float4(0.f, 0.f, 0.f, 0.f);
    float denom = 0.f;
    int idx = beg;
    for (; idx + 2 <= end; idx += 2) {
        int j0 = colv[idx], j1 = colv[idx + 1];
        float4 m0 = __ldg((const float4*)(xl + (size_t)j0 * HC1 + c4));
        float4 m1 = __ldg((const float4*)(xl + (size_t)j1 * HC1 + c4));
        m0.x += bl4.x; m0.y += bl4.y; m0.z += bl4.z; m0.w += bl4.w;
        m1.x += bl4.x; m1.y += bl4.y; m1.z += bl4.z; m1.w += bl4.w;
        float s0 = leaky(m0.x + xr4.x) * a4.x;
        s0 = fmaf(leaky(m0.y + xr4.y), a4.y, s0);
        s0 = fmaf(leaky(m0.z + xr4.z), a4.z, s0);
        s0 = fmaf(leaky(m0.w + xr4.w), a4.w, s0);
        float s1 = leaky(m1.x + xr4.x) * a4.x;
        s1 = fmaf(leaky(m1.y + xr4.y), a4.y, s1);
        s1 = fmaf(leaky(m1.z + xr4.z), a4.z, s1);
        s1 = fmaf(leaky(m1.w + xr4.w), a4.w, s1);
        #pragma unroll
        for (int o = 4; o; o >>= 1) {
            s0 += __shfl_xor_sync(0xffffffffu, s0, o);
            s1 += __shfl_xor_sync(0xffffffffu, s1, o);
        }
        float x0 = __expf(s0), x1 = __expf(s1);
        denom += x0 + x1;
        acc.x = fmaf(x0, m0.x, acc.x); acc.y = fmaf(x0, m0.y, acc.y);
        acc.z = fmaf(x0, m0.z, acc.z); acc.w = fmaf(x0, m0.w, acc.w);
        acc.x = fmaf(x1, m1.x, acc.x); acc.y = fmaf(x1, m1.y, acc.y);
        acc.z = fmaf(x1, m1.z, acc.z); acc.w = fmaf(x1, m1.w, acc.w);
    }
    if (idx < end) {
        int j = colv[idx];
        float4 m = __ldg((const float4*)(xl + (size_t)j * HC1 + c4));
        m.x += bl4.x; m.y += bl4.y; m.z += bl4.z; m.w += bl4.w;
        float s = leaky(m.x + xr4.x) * a4.x;
        s = fmaf(leaky(m.y + xr4.y), a4.y, s);
        s = fmaf(leaky(m.z + xr4.z), a4.z, s);
        s = fmaf(leaky(m.w + xr4.w), a4.w, s);
        #pragma unroll
        for (int o = 4; o; o >>= 1) s += __shfl_xor_sync(0xffffffffu, s, o);
        float ex = __expf(s);
        denom += ex;
        acc.x = fmaf(ex, m.x, acc.x); acc.y = fmaf(ex, m.y, acc.y);
        acc.z = fmaf(ex, m.z, acc.z); acc.w = fmaf(ex, m.w, acc.w);
    }
    float inv = 1.f / denom;
    float4 b4 = *(const float4*)(bias + c4);
    float4 o4;
    o4.x = fmaxf(fmaf(acc.x, inv, b4.x), 0.f);
    o4.y = fmaxf(fmaf(acc.y, inv, b4.y), 0.f);
    o4.z = fmaxf(fmaf(acc.z, inv, b4.z), 0.f);
    o4.w = fmaxf(fmaf(acc.w, inv, b4.w), 0.f);
    *(float4*)(out + (size_t)node * HC1 + c4) = o4;     // fused ReLU
}

// Layer 2: warp per node; two half-warps process two edges at once.
__global__ void __launch_bounds__(256)
attn_l2_k(const float* __restrict__ xl, const float* __restrict__ xr,
          const float* __restrict__ bl, const float* __restrict__ br,
          const float* __restrict__ att, const float* __restrict__ bias,
          const int* __restrict__ rowptr, const int* __restrict__ colv,
          float* __restrict__ out) {
    int node = (blockIdx.x * blockDim.x + threadIdx.x) >> 5;
    if (node >= N_NODES) return;
    int lane = threadIdx.x & 31;
    int half = lane >> 4;
    int sl   = lane & 15;
    int c4   = sl * 4;
    float4 a4  = *(const float4*)(att + c4);
    float4 bl4 = *(const float4*)(bl + c4);
    float4 xr4 = *(const float4*)(xr + (size_t)node * D_OUT + c4);
    {
        float4 br4 = *(const float4*)(br + c4);
        xr4.x += br4.x; xr4.y += br4.y; xr4.z += br4.z; xr4.w += br4.w;
    }
    int beg = rowptr[node], end = rowptr[node + 1];
    float4 acc = make_float4(0.f, 0.f, 0.f, 0.f);
    float denom = 0.f;
    for (int idx = beg; idx < end; idx += 2) {
        int e = idx + half;
        bool valid = (e < end);
        int j = colv[valid ? e : (end - 1)];
        float4 m = __ldg((const float4*)(xl + (size_t)j * D_OUT + c4));
        m.x += bl4.x; m.y += bl4.y; m.z += bl4.z; m.w += bl4.w;
        float s = leaky(m.x + xr4.x) * a4.x;
        s = fmaf(leaky(m.y + xr4.y), a4.y, s);
        s = fmaf(leaky(m.z + xr4.z), a4.z, s);
        s = fmaf(leaky(m.w + xr4.w), a4.w, s);
        #pragma unroll
        for (int o = 8; o; o >>= 1) s += __shfl_xor_sync(0xffffffffu, s, o);
        float ex = valid ? __expf(s) : 0.f;
        denom += ex;
        acc.x = fmaf(ex, m.x, acc.x); acc.y = fmaf(ex, m.y, acc.y);
        acc.z = fmaf(ex, m.z, acc.z); acc.w = fmaf(ex, m.w, acc.w);
    }
    denom += __shfl_xor_sync(0xffffffffu, denom, 16);
    acc.x += __shfl_xor_sync(0xffffffffu, acc.x, 16);
    acc.y += __shfl_xor_sync(0xffffffffu, acc.y, 16);
    acc.z += __shfl_xor_sync(0xffffffffu, acc.z, 16);
    acc.w += __shfl_xor_sync(0xffffffffu, acc.w, 16);
    if (half == 0) {
        float inv = 1.f / denom;
        float4 b4 = *(const float4*)(bias + c4);
        float4 o4;
        o4.x = fmaf(acc.x, inv, b4.x);
        o4.y = fmaf(acc.y, inv, b4.y);
        o4.z = fmaf(acc.z, inv, b4.z);
        o4.w = fmaf(acc.w, inv, b4.w);
        *(float4*)(out + (size_t)node * D_OUT + c4) = o4;
    }
}

// ---------------- host launcher ----------------
extern "C" void kernel_launch(void* const* d_in, const int* in_sizes, int n_in,
                              void* d_out, int out_size) {
    const float* x     = (const float*)d_in[0];
    const int*   ei    = (const int*)  d_in[1];
    const float* Wl1   = (const float*)d_in[2];
    const float* bl1   = (const float*)d_in[3];
    const float* Wr1   = (const float*)d_in[4];
    const float* br1   = (const float*)d_in[5];
    const float* att1  = (const float*)d_in[6];
    const float* bias1 = (const float*)d_in[7];
    const float* Wl2   = (const float*)d_in[8];
    const float* bl2   = (const float*)d_in[9];
    const float* Wr2   = (const float*)d_in[10];
    const float* br2   = (const float*)d_in[11];
    const float* att2  = (const float*)d_in[12];
    const float* bias2 = (const float*)d_in[13];
    float* out = (float*)d_out;

    float *xl, *xr, *h;
    int *counts, *cursor, *rowptr, *colv, *bsums;
    cudaGetSymbolAddress((void**)&xl,     g_xl);
    cudaGetSymbolAddress((void**)&xr,     g_xr);
    cudaGetSymbolAddress((void**)&h,      g_h);
    cudaGetSymbolAddress((void**)&counts, g_counts);
    cudaGetSymbolAddress((void**)&cursor, g_cursor);
    cudaGetSymbolAddress((void**)&rowptr, g_rowptr);
    cudaGetSymbolAddress((void**)&colv,   g_col);
    cudaGetSymbolAddress((void**)&bsums,  g_bsums);

    const int* srcv = ei;
    const int* dstv = ei + N_EDGES;

    // smem: A hi+lo [128][136] + 4 B planes [128][N+8], bf16
    const int smem1 = (2 * TM * LDA + 4 * GK * (HC1 + 8))   * 2;  // 208896 B
    const int smem2 = (2 * TM * LDA + 4 * GK * (D_OUT + 8)) * 2;  // 143360 B
    cudaFuncSetAttribute(gemm_tc_k,
        cudaFuncAttributeMaxDynamicSharedMemorySize, smem1);

    int attn_blocks = (N_NODES * 32 + 255) / 256;   // warp per node

    // gemm layer1 at kernel-launch index 3 (ncu capture window).
    cudaMemsetAsync(counts, 0, N_NODES * sizeof(int));
    cudaMemsetAsync(cursor, 0, N_NODES * sizeof(int));
    count_k     <<<(ET + 255) / 256, 256>>>(dstv, counts);                     // 0
    scan_block_k<<<NB, SCAN_T>>>(counts, rowptr, bsums, N_NODES);              // 1
    scan_sums_k <<<1, 64>>>(bsums);                                            // 2
    gemm_tc_k   <<<MTILES, 256, smem1>>>(x, Wl1, Wr1, xl, xr, N_NODES, HC1);   // 3
    scan_add_k  <<<NB, SCAN_T>>>(rowptr, bsums, N_NODES, ET);                  // 4
    scatter_k   <<<(ET + 255) / 256, 256>>>(srcv, dstv, rowptr, cursor, colv); // 5
    attn_l1_k   <<<attn_blocks, 256>>>(xl, xr, bl1, br1, att1, bias1,
                                       rowptr, colv, h);                       // 6
    gemm_tc_k   <<<MTILES, 256, smem2>>>(h, Wl2, Wr2, xl, xr, N_NODES, D_OUT); // 7
    attn_l2_k   <<<attn_blocks, 256>>>(xl, xr, bl2, br2, att2, bias2,
                                       rowptr, colv, out);                     // 8
}